// round 16
// baseline (speedup 1.0000x reference)
#include <cuda_runtime.h>
#include <cuda_fp16.h>
#include <cstdint>

// ---------------------------------------------------------------------------
// EncoderLayer: x -> MHA(flash) -> add&LN -> FF(relu) -> add&LN
// B=4, S=2048, D=1024, H=16, hd=64, FF=4096, fp32 in/out.
// Round 16: GEMM BK=64 per stage, 3-stage ring (half the barriers, proven
// ordering). Flash (BKV=64, 4-stage) as R15.
// ---------------------------------------------------------------------------

namespace cfg {
constexpr int D_MODEL = 1024;
constexpr int NHEADS  = 16;
constexpr int HDIM    = 64;
constexpr int DFF     = 4096;
constexpr int BATCH   = 4;
constexpr int SEQ     = 2048;
constexpr int NTOK    = BATCH * SEQ;   // 8192
}

// ------------------------------ scratch ------------------------------------
__device__ __half   g_xh[(size_t)cfg::NTOK * cfg::D_MODEL];
__device__ __half   g_qh[(size_t)cfg::NTOK * cfg::D_MODEL];   // pre-scaled by 1/8
__device__ __half   g_kh[(size_t)cfg::NTOK * cfg::D_MODEL];
__device__ __half   g_vh[(size_t)cfg::NTOK * cfg::D_MODEL];
__device__ __half   g_ah[(size_t)cfg::NTOK * cfg::D_MODEL];   // attn out fp16
__device__ __half   g_hh[(size_t)cfg::NTOK * cfg::D_MODEL];   // h fp16
__device__ __half   g_fh[(size_t)cfg::NTOK * cfg::DFF];       // relu(ff1) fp16
__device__ float    g_s1[(size_t)cfg::NTOK * cfg::D_MODEL];   // fp32 scratch
__device__ float    g_hf[(size_t)cfg::NTOK * cfg::D_MODEL];   // h fp32
// transposed fp16 weights: [N][K]
__device__ __half   g_wtq[(size_t)1024 * 1024];
__device__ __half   g_wtk[(size_t)1024 * 1024];
__device__ __half   g_wtv[(size_t)1024 * 1024];
__device__ __half   g_wto[(size_t)1024 * 1024];
__device__ __half   g_wt1[(size_t)4096 * 1024];
__device__ __half   g_wt2[(size_t)1024 * 4096];

// ------------------------------ helpers ------------------------------------
__device__ __forceinline__ void cp16(void* s, const void* g) {
    uint32_t sa = (uint32_t)__cvta_generic_to_shared(s);
    asm volatile("cp.async.cg.shared.global [%0], [%1], 16;\n" :: "r"(sa), "l"(g));
}
__device__ __forceinline__ void cp_commit() {
    asm volatile("cp.async.commit_group;\n");
}
template <int N>
__device__ __forceinline__ void cp_wait() {
    asm volatile("cp.async.wait_group %0;\n" :: "n"(N));
}
__device__ __forceinline__ void mma_f16(float* c, const uint32_t* a, const uint32_t* b) {
    asm volatile(
        "mma.sync.aligned.m16n8k16.row.col.f32.f16.f16.f32 "
        "{%0,%1,%2,%3}, {%4,%5,%6,%7}, {%8,%9}, {%0,%1,%2,%3};\n"
        : "+f"(c[0]), "+f"(c[1]), "+f"(c[2]), "+f"(c[3])
        : "r"(a[0]), "r"(a[1]), "r"(a[2]), "r"(a[3]),
          "r"(b[0]), "r"(b[1]));
}
__device__ __forceinline__ void ldsm_x4(uint32_t* r, uint32_t addr) {
    asm volatile(
        "ldmatrix.sync.aligned.m8n8.x4.shared.b16 {%0,%1,%2,%3}, [%4];"
        : "=r"(r[0]), "=r"(r[1]), "=r"(r[2]), "=r"(r[3]) : "r"(addr));
}
__device__ __forceinline__ void ldsm_x4_t(uint32_t* r, uint32_t addr) {
    asm volatile(
        "ldmatrix.sync.aligned.m8n8.x4.trans.shared.b16 {%0,%1,%2,%3}, [%4];"
        : "=r"(r[0]), "=r"(r[1]), "=r"(r[2]), "=r"(r[3]) : "r"(addr));
}

// ------------------------------ conversions --------------------------------
__global__ void __launch_bounds__(256) f2h_kernel(
    const float* __restrict__ in, __half* __restrict__ out)
{
    const size_t i = ((size_t)blockIdx.x * 256 + threadIdx.x) * 4;
    float4 v = *reinterpret_cast<const float4*>(in + i);
    __half2* o = reinterpret_cast<__half2*>(out + i);
    o[0] = __floats2half2_rn(v.x, v.y);
    o[1] = __floats2half2_rn(v.z, v.w);
}

// transpose fp32 [R][C] -> fp16 [C][R], tile origin (c0, r0)
__device__ __forceinline__ void wT_body(
    const float* __restrict__ in, __half* __restrict__ out,
    int R, int C, int c0, int r0)
{
    __shared__ float t[32][33];
    const int tx = threadIdx.x;
    const int ty = threadIdx.y;
    #pragma unroll
    for (int i = 0; i < 32; i += 8)
        t[ty + i][tx] = in[(size_t)(r0 + ty + i) * C + c0 + tx];
    __syncthreads();
    #pragma unroll
    for (int i = 0; i < 32; i += 8)
        out[(size_t)(c0 + ty + i) * R + r0 + tx] = __float2half_rn(t[tx][ty + i]);
}

__global__ void __launch_bounds__(256) wT4_kernel(
    const float* __restrict__ w0, __half* __restrict__ o0,
    const float* __restrict__ w1, __half* __restrict__ o1,
    const float* __restrict__ w2, __half* __restrict__ o2,
    const float* __restrict__ w3, __half* __restrict__ o3)
{
    const float* in;
    __half* out;
    switch (blockIdx.z) {
        case 0:  in = w0; out = o0; break;
        case 1:  in = w1; out = o1; break;
        case 2:  in = w2; out = o2; break;
        default: in = w3; out = o3; break;
    }
    wT_body(in, out, 1024, 1024, blockIdx.x * 32, blockIdx.y * 32);
}

__global__ void __launch_bounds__(256) wT2_kernel(
    const float* __restrict__ w1, __half* __restrict__ o1,
    const float* __restrict__ w2, __half* __restrict__ o2)
{
    if (blockIdx.z == 0)
        wT_body(w1, o1, 1024, 4096, blockIdx.x * 32, blockIdx.y * 32);
    else
        wT_body(w2, o2, 4096, 1024, blockIdx.y * 32, blockIdx.x * 32);
}

// ------------- GEMM (fp16 + ldmatrix, 128x128, BK=64, 3-stage) --------------
namespace gg {
constexpr int BM = 128, BN = 128, BK = 64, STG = 3;
constexpr int LDA = 72;   // halves per row (64 + 8 pad) = 144 B, conflict-free
constexpr int LDB = 72;
constexpr int A_TILE_HALVES = BM * LDA;             // 9216
constexpr int STAGE_HALVES  = 2 * A_TILE_HALVES;    // 18432
constexpr int STAGE_BYTES   = STAGE_HALVES * 2;     // 36864
constexpr int SMEM_BYTES    = STG * STAGE_BYTES;    // 110592
}

template <bool RELU, bool HOUT>
__device__ __forceinline__ void gemm_body(
    const __half* __restrict__ A, const __half* __restrict__ Wt,
    const float* __restrict__ bias, void* __restrict__ Cv,
    int N, int K, float oscale, __half* smh, int bm, int bn)
{
    using namespace gg;
    const int tid  = threadIdx.x;
    const int lane = tid & 31;
    const int warp = tid >> 5;
    const int wm   = warp & 1;
    const int wn   = warp >> 1;
    const int grp  = lane >> 2;
    const int tg   = lane & 3;

    const int ld_row = tid >> 1;          // 0..127
    const int ld_col = (tid & 1) * 32;    // halves

    auto issue = [&](int kt, int stg) {
        __half* sA = smh + stg * STAGE_HALVES;
        __half* sB = sA + A_TILE_HALVES;
        const int k0 = kt * BK;
        #pragma unroll
        for (int j = 0; j < 4; j++) {
            cp16(&sA[ld_row * LDA + ld_col + j * 8],
                 A  + (size_t)(bm + ld_row) * K + k0 + ld_col + j * 8);
            cp16(&sB[ld_row * LDB + ld_col + j * 8],
                 Wt + (size_t)(bn + ld_row) * K + k0 + ld_col + j * 8);
        }
    };

    const uint32_t smem_base = (uint32_t)__cvta_generic_to_shared(smh);
    const int aRow = lane & 15;
    const int aK   = (lane & 16) ? 8 : 0;
    const uint32_t aOff = (uint32_t)(((wm * 64 + aRow) * LDA + aK) * 2);
    const int bN = (lane & 7) + ((lane & 16) ? 8 : 0);
    const int bK = (lane & 8) ? 8 : 0;
    const uint32_t bOff = (uint32_t)(((wn * 32 + bN) * LDB + bK) * 2
                                     + A_TILE_HALVES * 2);

    float acc[4][4][4];
    #pragma unroll
    for (int mi = 0; mi < 4; mi++)
        #pragma unroll
        for (int ni = 0; ni < 4; ni++)
            #pragma unroll
            for (int j = 0; j < 4; j++) acc[mi][ni][j] = 0.f;

    const int ntiles = K / BK;   // 16 (K=1024) or 64 (K=4096)
    issue(0, 0); cp_commit();
    issue(1, 1); cp_commit();

    int stg = 2;
    for (int kt = 0; kt < ntiles; kt++) {
        cp_wait<1>();
        __syncthreads();
        if (kt + 2 < ntiles) issue(kt + 2, stg);
        cp_commit();

        const int cs = kt - (kt / 3) * 3;   // kt % 3
        const uint32_t stageA = smem_base + cs * STAGE_BYTES + aOff;
        const uint32_t stageB = smem_base + cs * STAGE_BYTES + bOff;

        #pragma unroll
        for (int ks = 0; ks < 4; ks++) {
            uint32_t af[4][4];
            #pragma unroll
            for (int mi = 0; mi < 4; mi++)
                ldsm_x4(af[mi], stageA + (mi * 16 * LDA + ks * 16) * 2);
            uint32_t bf[4][2];
            #pragma unroll
            for (int np = 0; np < 2; np++) {
                uint32_t r[4];
                ldsm_x4(r, stageB + (np * 16 * LDB + ks * 16) * 2);
                bf[np * 2    ][0] = r[0]; bf[np * 2    ][1] = r[1];
                bf[np * 2 + 1][0] = r[2]; bf[np * 2 + 1][1] = r[3];
            }
            #pragma unroll
            for (int mi = 0; mi < 4; mi++)
                #pragma unroll
                for (int ni = 0; ni < 4; ni++)
                    mma_f16(acc[mi][ni], af[mi], bf[ni]);
        }
        stg = cs;   // stage just consumed becomes next fill target
    }

    #pragma unroll
    for (int mi = 0; mi < 4; mi++) {
        const int r0 = bm + wm * 64 + mi * 16 + grp;
        #pragma unroll
        for (int ni = 0; ni < 4; ni++) {
            const int c0 = bn + wn * 32 + ni * 8 + tg * 2;
            const float bv0 = __ldg(&bias[c0]);
            const float bv1 = __ldg(&bias[c0 + 1]);
            float v0 = (acc[mi][ni][0] + bv0) * oscale;
            float v1 = (acc[mi][ni][1] + bv1) * oscale;
            float v2 = (acc[mi][ni][2] + bv0) * oscale;
            float v3 = (acc[mi][ni][3] + bv1) * oscale;
            if (RELU) {
                v0 = fmaxf(v0, 0.f); v1 = fmaxf(v1, 0.f);
                v2 = fmaxf(v2, 0.f); v3 = fmaxf(v3, 0.f);
            }
            if (HOUT) {
                __half* Ch = (__half*)Cv;
                *reinterpret_cast<__half2*>(&Ch[(size_t)r0 * N + c0]) =
                    __floats2half2_rn(v0, v1);
                *reinterpret_cast<__half2*>(&Ch[(size_t)(r0 + 8) * N + c0]) =
                    __floats2half2_rn(v2, v3);
            } else {
                float* Cf = (float*)Cv;
                *reinterpret_cast<float2*>(&Cf[(size_t)r0 * N + c0]) =
                    make_float2(v0, v1);
                *reinterpret_cast<float2*>(&Cf[(size_t)(r0 + 8) * N + c0]) =
                    make_float2(v2, v3);
            }
        }
    }
}

template <bool RELU, bool HOUT>
__global__ void __launch_bounds__(256, 2) gemm_h(
    const __half* __restrict__ A, const __half* __restrict__ Wt,
    const float* __restrict__ bias, void* __restrict__ C,
    int N, int K, float oscale)
{
    extern __shared__ __half smh[];
    gemm_body<RELU, HOUT>(A, Wt, bias, C, N, K, oscale, smh,
                          blockIdx.y * gg::BM, blockIdx.x * gg::BN);
}

__global__ void __launch_bounds__(256, 2) gemm_qkv_h(
    const __half* __restrict__ X,
    const __half* __restrict__ Wq, const float* __restrict__ bq, __half* __restrict__ q,
    const __half* __restrict__ Wk, const float* __restrict__ bk, __half* __restrict__ k,
    const __half* __restrict__ Wv, const float* __restrict__ bv, __half* __restrict__ v)
{
    extern __shared__ __half smh[];
    const __half* W;
    const float* bi;
    __half* C;
    float sc = 1.f;
    if (blockIdx.z == 0)      { W = Wq; bi = bq; C = q; sc = 0.125f; }
    else if (blockIdx.z == 1) { W = Wk; bi = bk; C = k; }
    else                      { W = Wv; bi = bv; C = v; }
    gemm_body<false, true>(X, W, bi, C, cfg::D_MODEL, cfg::D_MODEL, sc, smh,
                           blockIdx.y * gg::BM, blockIdx.x * gg::BN);
}

// ---------- flash attention (fp16, BKV=64, 4-stage, ldmatrix V) -------------
namespace fa {
constexpr int BQ  = 128;
constexpr int BKV = 64;
constexpr int STG = 4;
constexpr int LDK  = 36;   // u32 per K token row (32 d-pairs + 4)
constexpr int LDVH = 72;   // halves per V token row (64 + 8 pad) = 144 B
constexpr int LDP  = 36;   // u32 per P row (32 token-pairs + 4)
constexpr int K_STAGE_U32 = BKV * LDK;        // 2304
constexpr int V_STAGE_U32 = BKV * LDVH / 2;   // 2304
constexpr int SMEM_U32 = STG * (K_STAGE_U32 + V_STAGE_U32) + BQ * LDP; // 23040
constexpr int SMEM_BYTES = SMEM_U32 * 4;      // 92160
}

__global__ void __launch_bounds__(256, 2) flash_h(
    const __half* __restrict__ Q, const __half* __restrict__ K,
    const __half* __restrict__ V, __half* __restrict__ O)
{
    using namespace fa;
    extern __shared__ uint32_t sm[];
    uint32_t* Ks = sm;
    uint32_t* Vs = sm + STG * K_STAGE_U32;
    uint32_t* Ps = Vs + STG * V_STAGE_U32;
    __half*   Vsh = reinterpret_cast<__half*>(Vs);

    const int tid  = threadIdx.x;
    const int lane = tid & 31;
    const int warp = tid >> 5;
    const int grp  = lane >> 2;
    const int tg   = lane & 3;
    const int bh   = blockIdx.y;
    const int b    = bh >> 4;
    const int h    = bh & 15;
    const int bm   = blockIdx.x * BQ;
    const int wrow = warp * 16;

    const __half* Kp = K + (size_t)b * cfg::SEQ * 1024 + h * 64;
    const __half* Vp = V + (size_t)b * cfg::SEQ * 1024 + h * 64;

    // Q fragments direct from gmem (pre-scaled fp16)
    uint32_t qf[4][4];
    {
        const size_t tok0 = (size_t)b * cfg::SEQ + bm + wrow + grp;
        const uint32_t* q0 = reinterpret_cast<const uint32_t*>(
            Q + tok0 * 1024 + h * 64);
        const uint32_t* q1 = reinterpret_cast<const uint32_t*>(
            Q + (tok0 + 8) * 1024 + h * 64);
        #pragma unroll
        for (int ks = 0; ks < 4; ks++) {
            qf[ks][0] = q0[ks * 8 + tg    ];
            qf[ks][1] = q1[ks * 8 + tg    ];
            qf[ks][2] = q0[ks * 8 + tg + 4];
            qf[ks][3] = q1[ks * 8 + tg + 4];
        }
    }

    const int krow  = tid >> 3;           // 0..31
    const int kcol  = (tid & 7) * 4;      // u32
    const int vcolh = (tid & 7) * 8;      // halves

    auto issue_kv = [&](int t) {
        const int bf = t & (STG - 1);
        #pragma unroll
        for (int i = 0; i < 2; i++) {
            int r = krow + i * 32;
            cp16(&Ks[(bf * BKV + r) * LDK + kcol],
                 Kp + (size_t)(t * BKV + r) * 1024 + kcol * 2);
            cp16(&Vsh[(bf * BKV + r) * LDVH + vcolh],
                 Vp + (size_t)(t * BKV + r) * 1024 + vcolh);
        }
    };

    issue_kv(0); cp_commit();
    issue_kv(1); cp_commit();
    issue_kv(2); cp_commit();

    // ldmatrix lane mappings
    const uint32_t KsBase = (uint32_t)__cvta_generic_to_shared(Ks);
    const int kTok = (lane & 7) + ((lane & 16) ? 8 : 0);
    const int kOffU = (lane & 8) ? 4 : 0;
    const uint32_t kLane = (uint32_t)((kTok * LDK + kOffU) * 4);

    const uint32_t VsBase = (uint32_t)__cvta_generic_to_shared(Vs);
    const uint32_t vLane = (uint32_t)(((lane & 15) * LDVH
                                       + ((lane & 16) ? 8 : 0)) * 2);

    const uint32_t PsBase = (uint32_t)__cvta_generic_to_shared(Ps);
    const uint32_t pLane = (uint32_t)(((wrow + (lane & 15)) * LDP
                                       + ((lane & 16) ? 4 : 0)) * 4);

    float oacc[8][4];
    #pragma unroll
    for (int ni = 0; ni < 8; ni++)
        #pragma unroll
        for (int j = 0; j < 4; j++) oacc[ni][j] = 0.f;
    float m0 = -3.402823466e38f, m1 = -3.402823466e38f;
    float l0 = 0.f, l1 = 0.f;

    constexpr int NT = cfg::SEQ / BKV;   // 32
    for (int t = 0; t < NT; t++) {
        cp_wait<2>();
        __syncthreads();
        if (t + 3 < NT) issue_kv(t + 3);
        cp_commit();

        const int buf = t & (STG - 1);

        // ---- S = Qs @ K^T  (128 x 64, k=64 dims) ----
        float sacc[8][4];
        #pragma unroll
        for (int ni = 0; ni < 8; ni++)
            #pragma unroll
            for (int j = 0; j < 4; j++) sacc[ni][j] = 0.f;

        const uint32_t kStage = KsBase + (uint32_t)(buf * K_STAGE_U32 * 4) + kLane;
        #pragma unroll
        for (int ks = 0; ks < 4; ks++) {
            uint32_t bf[8][2];
            #pragma unroll
            for (int ng = 0; ng < 4; ng++) {
                uint32_t r[4];
                ldsm_x4(r, kStage + (uint32_t)((ng * 16 * LDK + ks * 8) * 4));
                bf[ng * 2    ][0] = r[0]; bf[ng * 2    ][1] = r[1];
                bf[ng * 2 + 1][0] = r[2]; bf[ng * 2 + 1][1] = r[3];
            }
            #pragma unroll
            for (int ni = 0; ni < 8; ni++)
                mma_f16(sacc[ni], qf[ks], bf[ni]);
        }

        // ---- online softmax (rows grp / grp+8) ----
        float mx0 = -3.402823466e38f, mx1 = -3.402823466e38f;
        #pragma unroll
        for (int ni = 0; ni < 8; ni++) {
            mx0 = fmaxf(mx0, fmaxf(sacc[ni][0], sacc[ni][1]));
            mx1 = fmaxf(mx1, fmaxf(sacc[ni][2], sacc[ni][3]));
        }
        mx0 = fmaxf(mx0, __shfl_xor_sync(0xffffffffu, mx0, 1));
        mx0 = fmaxf(mx0, __shfl_xor_sync(0xffffffffu, mx0, 2));
        mx1 = fmaxf(mx1, __shfl_xor_sync(0xffffffffu, mx1, 1));
        mx1 = fmaxf(mx1, __shfl_xor_sync(0xffffffffu, mx1, 2));

        const float mn0 = fmaxf(m0, mx0);
        const float mn1 = fmaxf(m1, mx1);
        const float a0  = __expf(m0 - mn0);
        const float a1  = __expf(m1 - mn1);
        m0 = mn0; m1 = mn1;

        float rs0 = 0.f, rs1 = 0.f;
        #pragma unroll
        for (int ni = 0; ni < 8; ni++) {
            float p0 = __expf(sacc[ni][0] - m0);
            float p1 = __expf(sacc[ni][1] - m0);
            float p2 = __expf(sacc[ni][2] - m1);
            float p3 = __expf(sacc[ni][3] - m1);
            rs0 += p0 + p1;
            rs1 += p2 + p3;
            __half2 hA = __floats2half2_rn(p0, p1);
            __half2 hB = __floats2half2_rn(p2, p3);
            Ps[(wrow + grp    ) * LDP + ni * 4 + tg] = *reinterpret_cast<uint32_t*>(&hA);
            Ps[(wrow + grp + 8) * LDP + ni * 4 + tg] = *reinterpret_cast<uint32_t*>(&hB);
        }
        l0 = l0 * a0 + rs0;
        l1 = l1 * a1 + rs1;
        #pragma unroll
        for (int ni = 0; ni < 8; ni++) {
            oacc[ni][0] *= a0; oacc[ni][1] *= a0;
            oacc[ni][2] *= a1; oacc[ni][3] *= a1;
        }
        __syncwarp();

        // ---- O += P @ V  (k = 64 tokens); P via ldmatrix, V via ldmatrix.trans
        const uint32_t vStage = VsBase + (uint32_t)(buf * V_STAGE_U32 * 4) + vLane;
        #pragma unroll
        for (int ks = 0; ks < 4; ks++) {
            uint32_t af[4];
            ldsm_x4(af, PsBase + pLane + (uint32_t)(ks * 8 * 4));
            #pragma unroll
            for (int ng = 0; ng < 4; ng++) {
                uint32_t r[4];
                ldsm_x4_t(r, vStage + (uint32_t)((ks * 16 * LDVH + ng * 16) * 2));
                mma_f16(oacc[ng * 2    ], af, &r[0]);
                mma_f16(oacc[ng * 2 + 1], af, &r[2]);
            }
        }
        __syncwarp();
    }

    l0 += __shfl_xor_sync(0xffffffffu, l0, 1);
    l0 += __shfl_xor_sync(0xffffffffu, l0, 2);
    l1 += __shfl_xor_sync(0xffffffffu, l1, 1);
    l1 += __shfl_xor_sync(0xffffffffu, l1, 2);
    const float inv0 = 1.f / l0;
    const float inv1 = 1.f / l1;

    const size_t tok0 = (size_t)b * cfg::SEQ + bm + wrow + grp;
    #pragma unroll
    for (int ni = 0; ni < 8; ni++) {
        const int c = h * 64 + ni * 8 + tg * 2;
        *reinterpret_cast<__half2*>(&O[tok0 * 1024 + c]) =
            __floats2half2_rn(oacc[ni][0] * inv0, oacc[ni][1] * inv0);
        *reinterpret_cast<__half2*>(&O[(tok0 + 8) * 1024 + c]) =
            __floats2half2_rn(oacc[ni][2] * inv1, oacc[ni][3] * inv1);
    }
}

// ------------------------------ add + LayerNorm ----------------------------
template <bool DUAL>
__global__ void __launch_bounds__(256) add_ln_kernel(
    const float* __restrict__ a, const float* __restrict__ b,
    const float* __restrict__ gamma, const float* __restrict__ beta,
    float* __restrict__ outp, __half* __restrict__ outh)
{
    const size_t row = blockIdx.x;
    const float* pa = a + row * cfg::D_MODEL;
    const float* pb = b + row * cfg::D_MODEL;
    float* po = outp + row * cfg::D_MODEL;
    __half* ph = DUAL ? outh + row * cfg::D_MODEL : nullptr;
    const int tid = threadIdx.x;

    float v[4];
    float s = 0.f, sq = 0.f;
    #pragma unroll
    for (int i = 0; i < 4; i++) {
        const int c = i * 256 + tid;
        v[i] = pa[c] + pb[c];
        s += v[i];
        sq += v[i] * v[i];
    }

    __shared__ float r1[8], r2[8];
    #pragma unroll
    for (int o = 16; o > 0; o >>= 1) {
        s  += __shfl_xor_sync(0xffffffffu, s, o);
        sq += __shfl_xor_sync(0xffffffffu, sq, o);
    }
    if ((tid & 31) == 0) { r1[tid >> 5] = s; r2[tid >> 5] = sq; }
    __syncthreads();
    s = 0.f; sq = 0.f;
    #pragma unroll
    for (int j = 0; j < 8; j++) { s += r1[j]; sq += r2[j]; }

    const float mu   = s * (1.f / cfg::D_MODEL);
    const float var  = sq * (1.f / cfg::D_MODEL) - mu * mu;
    const float rstd = rsqrtf(var + 1e-5f);

    #pragma unroll
    for (int i = 0; i < 4; i++) {
        const int c = i * 256 + tid;
        const float r = (v[i] - mu) * rstd * __ldg(&gamma[c]) + __ldg(&beta[c]);
        po[c] = r;
        if (DUAL) ph[c] = __float2half_rn(r);
    }
}

// ------------------------------ launch -------------------------------------
extern "C" void kernel_launch(void* const* d_in, const int* in_sizes, int n_in,
                              void* d_out, int out_size)
{
    using namespace cfg;
    const float* x   = (const float*)d_in[0];
    const float* Wq  = (const float*)d_in[1];
    const float* bq  = (const float*)d_in[2];
    const float* Wk  = (const float*)d_in[3];
    const float* bk_ = (const float*)d_in[4];
    const float* Wv  = (const float*)d_in[5];
    const float* bv  = (const float*)d_in[6];
    const float* Wo  = (const float*)d_in[7];
    const float* bo  = (const float*)d_in[8];
    const float* W1  = (const float*)d_in[9];
    const float* b1  = (const float*)d_in[10];
    const float* W2  = (const float*)d_in[11];
    const float* b2  = (const float*)d_in[12];
    const float* g1  = (const float*)d_in[13];
    const float* be1 = (const float*)d_in[14];
    const float* g2  = (const float*)d_in[15];
    const float* be2 = (const float*)d_in[16];
    float* out = (float*)d_out;

    __half *xh, *qh, *kh, *vh, *ah, *hh, *fh;
    __half *wtq, *wtk, *wtv, *wto, *wt1, *wt2;
    float *s1, *hf;
    cudaGetSymbolAddress((void**)&xh,  g_xh);
    cudaGetSymbolAddress((void**)&qh,  g_qh);
    cudaGetSymbolAddress((void**)&kh,  g_kh);
    cudaGetSymbolAddress((void**)&vh,  g_vh);
    cudaGetSymbolAddress((void**)&ah,  g_ah);
    cudaGetSymbolAddress((void**)&hh,  g_hh);
    cudaGetSymbolAddress((void**)&fh,  g_fh);
    cudaGetSymbolAddress((void**)&s1,  g_s1);
    cudaGetSymbolAddress((void**)&hf,  g_hf);
    cudaGetSymbolAddress((void**)&wtq, g_wtq);
    cudaGetSymbolAddress((void**)&wtk, g_wtk);
    cudaGetSymbolAddress((void**)&wtv, g_wtv);
    cudaGetSymbolAddress((void**)&wto, g_wto);
    cudaGetSymbolAddress((void**)&wt1, g_wt1);
    cudaGetSymbolAddress((void**)&wt2, g_wt2);

    static bool attr_done = false;
    if (!attr_done) {
        cudaFuncSetAttribute(flash_h,
                             cudaFuncAttributeMaxDynamicSharedMemorySize,
                             fa::SMEM_BYTES);
        cudaFuncSetAttribute(gemm_h<false, false>,
                             cudaFuncAttributeMaxDynamicSharedMemorySize,
                             gg::SMEM_BYTES);
        cudaFuncSetAttribute(gemm_h<true, true>,
                             cudaFuncAttributeMaxDynamicSharedMemorySize,
                             gg::SMEM_BYTES);
        cudaFuncSetAttribute(gemm_qkv_h,
                             cudaFuncAttributeMaxDynamicSharedMemorySize,
                             gg::SMEM_BYTES);
        attr_done = true;
    }

    // 0) conversions: x -> fp16; weights -> transposed fp16 [N][K]
    f2h_kernel<<<(NTOK * D_MODEL) / 1024, 256>>>(x, xh);
    {
        dim3 blk(32, 8);
        wT4_kernel<<<dim3(32, 32, 4), blk>>>(Wq, wtq, Wk, wtk, Wv, wtv, Wo, wto);
        wT2_kernel<<<dim3(128, 32, 2), blk>>>(W1, wt1, W2, wt2);
    }

    // 1) QKV projections (q pre-scaled by 1/8), fp16 outputs
    {
        dim3 grid(D_MODEL / gg::BN, NTOK / gg::BM, 3);
        gemm_qkv_h<<<grid, 256, gg::SMEM_BYTES>>>(
            xh, wtq, bq, qh, wtk, bk_, kh, wtv, bv, vh);
    }

    // 2-4) flash attention -> ah (fp16)
    {
        dim3 grid(SEQ / fa::BQ, BATCH * NHEADS);
        flash_h<<<grid, 256, fa::SMEM_BYTES>>>(qh, kh, vh, ah);
    }

    // 5) output projection -> s1 (fp32)
    {
        dim3 grid(D_MODEL / gg::BN, NTOK / gg::BM);
        gemm_h<false, false><<<grid, 256, gg::SMEM_BYTES>>>(
            ah, wto, bo, s1, D_MODEL, D_MODEL, 1.f);
    }

    // 6) h = LN(x + s1): fp32 + fp16 outputs
    add_ln_kernel<true><<<NTOK, 256>>>(x, s1, g1, be1, hf, hh);

    // 7) ff = relu(h @ W1 + b1) -> fh (fp16)
    {
        dim3 grid(DFF / gg::BN, NTOK / gg::BM);
        gemm_h<true, true><<<grid, 256, gg::SMEM_BYTES>>>(
            hh, wt1, b1, fh, DFF, D_MODEL, 1.f);
    }

    // 8) ff2 = fh @ W2 + b2 -> s1 (fp32)
    {
        dim3 grid(D_MODEL / gg::BN, NTOK / gg::BM);
        gemm_h<false, false><<<grid, 256, gg::SMEM_BYTES>>>(
            fh, wt2, b2, s1, D_MODEL, DFF, 1.f);
    }

    // 9) out = LN(h + ff2)
    add_ln_kernel<false><<<NTOK, 256>>>(hf, s1, g2, be2, out, nullptr);
}

// round 17
// speedup vs baseline: 1.2298x; 1.2298x over previous
#include <cuda_runtime.h>
#include <cuda_fp16.h>
#include <cstdint>

// ---------------------------------------------------------------------------
// EncoderLayer: x -> MHA(flash) -> add&LN -> FF(relu) -> add&LN
// B=4, S=2048, D=1024, H=16, hd=64, FF=4096, fp32 in/out.
// Round 17: validated optimum (R15). fp16 m16n8k16 + ldmatrix everywhere;
// GEMM 128x128 BK=32 4-stage cp.async @ 2 CTAs/SM; flash BKV=64 4-stage
// with ldmatrix K/P and ldmatrix.trans V; fused dual-precision add+LN.
// ---------------------------------------------------------------------------

namespace cfg {
constexpr int D_MODEL = 1024;
constexpr int NHEADS  = 16;
constexpr int HDIM    = 64;
constexpr int DFF     = 4096;
constexpr int BATCH   = 4;
constexpr int SEQ     = 2048;
constexpr int NTOK    = BATCH * SEQ;   // 8192
}

// ------------------------------ scratch ------------------------------------
__device__ __half   g_xh[(size_t)cfg::NTOK * cfg::D_MODEL];
__device__ __half   g_qh[(size_t)cfg::NTOK * cfg::D_MODEL];   // pre-scaled by 1/8
__device__ __half   g_kh[(size_t)cfg::NTOK * cfg::D_MODEL];
__device__ __half   g_vh[(size_t)cfg::NTOK * cfg::D_MODEL];
__device__ __half   g_ah[(size_t)cfg::NTOK * cfg::D_MODEL];   // attn out fp16
__device__ __half   g_hh[(size_t)cfg::NTOK * cfg::D_MODEL];   // h fp16
__device__ __half   g_fh[(size_t)cfg::NTOK * cfg::DFF];       // relu(ff1) fp16
__device__ float    g_s1[(size_t)cfg::NTOK * cfg::D_MODEL];   // fp32 scratch
__device__ float    g_hf[(size_t)cfg::NTOK * cfg::D_MODEL];   // h fp32
// transposed fp16 weights: [N][K]
__device__ __half   g_wtq[(size_t)1024 * 1024];
__device__ __half   g_wtk[(size_t)1024 * 1024];
__device__ __half   g_wtv[(size_t)1024 * 1024];
__device__ __half   g_wto[(size_t)1024 * 1024];
__device__ __half   g_wt1[(size_t)4096 * 1024];
__device__ __half   g_wt2[(size_t)1024 * 4096];

// ------------------------------ helpers ------------------------------------
__device__ __forceinline__ void cp16(void* s, const void* g) {
    uint32_t sa = (uint32_t)__cvta_generic_to_shared(s);
    asm volatile("cp.async.cg.shared.global [%0], [%1], 16;\n" :: "r"(sa), "l"(g));
}
__device__ __forceinline__ void cp_commit() {
    asm volatile("cp.async.commit_group;\n");
}
template <int N>
__device__ __forceinline__ void cp_wait() {
    asm volatile("cp.async.wait_group %0;\n" :: "n"(N));
}
__device__ __forceinline__ void mma_f16(float* c, const uint32_t* a, const uint32_t* b) {
    asm volatile(
        "mma.sync.aligned.m16n8k16.row.col.f32.f16.f16.f32 "
        "{%0,%1,%2,%3}, {%4,%5,%6,%7}, {%8,%9}, {%0,%1,%2,%3};\n"
        : "+f"(c[0]), "+f"(c[1]), "+f"(c[2]), "+f"(c[3])
        : "r"(a[0]), "r"(a[1]), "r"(a[2]), "r"(a[3]),
          "r"(b[0]), "r"(b[1]));
}
__device__ __forceinline__ void ldsm_x4(uint32_t* r, uint32_t addr) {
    asm volatile(
        "ldmatrix.sync.aligned.m8n8.x4.shared.b16 {%0,%1,%2,%3}, [%4];"
        : "=r"(r[0]), "=r"(r[1]), "=r"(r[2]), "=r"(r[3]) : "r"(addr));
}
__device__ __forceinline__ void ldsm_x4_t(uint32_t* r, uint32_t addr) {
    asm volatile(
        "ldmatrix.sync.aligned.m8n8.x4.trans.shared.b16 {%0,%1,%2,%3}, [%4];"
        : "=r"(r[0]), "=r"(r[1]), "=r"(r[2]), "=r"(r[3]) : "r"(addr));
}

// ------------------------------ conversions --------------------------------
__global__ void __launch_bounds__(256) f2h_kernel(
    const float* __restrict__ in, __half* __restrict__ out)
{
    const size_t i = ((size_t)blockIdx.x * 256 + threadIdx.x) * 4;
    float4 v = *reinterpret_cast<const float4*>(in + i);
    __half2* o = reinterpret_cast<__half2*>(out + i);
    o[0] = __floats2half2_rn(v.x, v.y);
    o[1] = __floats2half2_rn(v.z, v.w);
}

// transpose fp32 [R][C] -> fp16 [C][R], tile origin (c0, r0)
__device__ __forceinline__ void wT_body(
    const float* __restrict__ in, __half* __restrict__ out,
    int R, int C, int c0, int r0)
{
    __shared__ float t[32][33];
    const int tx = threadIdx.x;
    const int ty = threadIdx.y;
    #pragma unroll
    for (int i = 0; i < 32; i += 8)
        t[ty + i][tx] = in[(size_t)(r0 + ty + i) * C + c0 + tx];
    __syncthreads();
    #pragma unroll
    for (int i = 0; i < 32; i += 8)
        out[(size_t)(c0 + ty + i) * R + r0 + tx] = __float2half_rn(t[tx][ty + i]);
}

__global__ void __launch_bounds__(256) wT4_kernel(
    const float* __restrict__ w0, __half* __restrict__ o0,
    const float* __restrict__ w1, __half* __restrict__ o1,
    const float* __restrict__ w2, __half* __restrict__ o2,
    const float* __restrict__ w3, __half* __restrict__ o3)
{
    const float* in;
    __half* out;
    switch (blockIdx.z) {
        case 0:  in = w0; out = o0; break;
        case 1:  in = w1; out = o1; break;
        case 2:  in = w2; out = o2; break;
        default: in = w3; out = o3; break;
    }
    wT_body(in, out, 1024, 1024, blockIdx.x * 32, blockIdx.y * 32);
}

__global__ void __launch_bounds__(256) wT2_kernel(
    const float* __restrict__ w1, __half* __restrict__ o1,
    const float* __restrict__ w2, __half* __restrict__ o2)
{
    if (blockIdx.z == 0)
        wT_body(w1, o1, 1024, 4096, blockIdx.x * 32, blockIdx.y * 32);
    else
        wT_body(w2, o2, 4096, 1024, blockIdx.y * 32, blockIdx.x * 32);
}

// ------------- GEMM (fp16 + ldmatrix, 128x128, 4-stage, per-tile) -----------
namespace gg {
constexpr int BM = 128, BN = 128, BK = 32, STG = 4;
constexpr int LDA = 40;   // halves per row (32 + 8 pad)
constexpr int LDB = 40;
constexpr int A_TILE_HALVES = BM * LDA;             // 5120
constexpr int STAGE_HALVES  = 2 * A_TILE_HALVES;    // 10240
constexpr int STAGE_BYTES   = STAGE_HALVES * 2;     // 20480
constexpr int SMEM_BYTES    = STG * STAGE_BYTES;    // 81920
}

template <bool RELU, bool HOUT>
__device__ __forceinline__ void gemm_body(
    const __half* __restrict__ A, const __half* __restrict__ Wt,
    const float* __restrict__ bias, void* __restrict__ Cv,
    int N, int K, float oscale, __half* smh, int bm, int bn)
{
    using namespace gg;
    const int tid  = threadIdx.x;
    const int lane = tid & 31;
    const int warp = tid >> 5;
    const int wm   = warp & 1;
    const int wn   = warp >> 1;
    const int grp  = lane >> 2;
    const int tg   = lane & 3;

    const int ld_row = tid >> 2;
    const int ld_col = (tid & 3) * 8;

    auto issue = [&](int kt) {
        __half* sA = smh + (kt & (STG - 1)) * STAGE_HALVES;
        __half* sB = sA + A_TILE_HALVES;
        const int k0 = kt * BK;
        #pragma unroll
        for (int i = 0; i < 2; i++) {
            int r = ld_row + i * 64;
            cp16(&sA[r * LDA + ld_col], A  + (size_t)(bm + r) * K + k0 + ld_col);
            cp16(&sB[r * LDB + ld_col], Wt + (size_t)(bn + r) * K + k0 + ld_col);
        }
    };

    const uint32_t smem_base = (uint32_t)__cvta_generic_to_shared(smh);
    const int aRow = lane & 15;
    const int aK   = (lane & 16) ? 8 : 0;
    const uint32_t aOff = (uint32_t)(((wm * 64 + aRow) * LDA + aK) * 2);
    const int bN = (lane & 7) + ((lane & 16) ? 8 : 0);
    const int bK = (lane & 8) ? 8 : 0;
    const uint32_t bOff = (uint32_t)(((wn * 32 + bN) * LDB + bK) * 2
                                     + A_TILE_HALVES * 2);

    float acc[4][4][4];
    #pragma unroll
    for (int mi = 0; mi < 4; mi++)
        #pragma unroll
        for (int ni = 0; ni < 4; ni++)
            #pragma unroll
            for (int j = 0; j < 4; j++) acc[mi][ni][j] = 0.f;

    const int ntiles = K / BK;
    issue(0); cp_commit();
    issue(1); cp_commit();
    issue(2); cp_commit();

    for (int kt = 0; kt < ntiles; kt++) {
        cp_wait<2>();
        __syncthreads();
        if (kt + 3 < ntiles) issue(kt + 3);
        cp_commit();

        const int cs = kt & (STG - 1);
        const uint32_t stageA = smem_base + cs * STAGE_BYTES + aOff;
        const uint32_t stageB = smem_base + cs * STAGE_BYTES + bOff;

        #pragma unroll
        for (int ks = 0; ks < 2; ks++) {
            uint32_t af[4][4];
            #pragma unroll
            for (int mi = 0; mi < 4; mi++)
                ldsm_x4(af[mi], stageA + (mi * 16 * LDA + ks * 16) * 2);
            uint32_t bf[4][2];
            #pragma unroll
            for (int np = 0; np < 2; np++) {
                uint32_t r[4];
                ldsm_x4(r, stageB + (np * 16 * LDB + ks * 16) * 2);
                bf[np * 2    ][0] = r[0]; bf[np * 2    ][1] = r[1];
                bf[np * 2 + 1][0] = r[2]; bf[np * 2 + 1][1] = r[3];
            }
            #pragma unroll
            for (int mi = 0; mi < 4; mi++)
                #pragma unroll
                for (int ni = 0; ni < 4; ni++)
                    mma_f16(acc[mi][ni], af[mi], bf[ni]);
        }
    }

    #pragma unroll
    for (int mi = 0; mi < 4; mi++) {
        const int r0 = bm + wm * 64 + mi * 16 + grp;
        #pragma unroll
        for (int ni = 0; ni < 4; ni++) {
            const int c0 = bn + wn * 32 + ni * 8 + tg * 2;
            const float bv0 = __ldg(&bias[c0]);
            const float bv1 = __ldg(&bias[c0 + 1]);
            float v0 = (acc[mi][ni][0] + bv0) * oscale;
            float v1 = (acc[mi][ni][1] + bv1) * oscale;
            float v2 = (acc[mi][ni][2] + bv0) * oscale;
            float v3 = (acc[mi][ni][3] + bv1) * oscale;
            if (RELU) {
                v0 = fmaxf(v0, 0.f); v1 = fmaxf(v1, 0.f);
                v2 = fmaxf(v2, 0.f); v3 = fmaxf(v3, 0.f);
            }
            if (HOUT) {
                __half* Ch = (__half*)Cv;
                *reinterpret_cast<__half2*>(&Ch[(size_t)r0 * N + c0]) =
                    __floats2half2_rn(v0, v1);
                *reinterpret_cast<__half2*>(&Ch[(size_t)(r0 + 8) * N + c0]) =
                    __floats2half2_rn(v2, v3);
            } else {
                float* Cf = (float*)Cv;
                *reinterpret_cast<float2*>(&Cf[(size_t)r0 * N + c0]) =
                    make_float2(v0, v1);
                *reinterpret_cast<float2*>(&Cf[(size_t)(r0 + 8) * N + c0]) =
                    make_float2(v2, v3);
            }
        }
    }
}

template <bool RELU, bool HOUT>
__global__ void __launch_bounds__(256, 2) gemm_h(
    const __half* __restrict__ A, const __half* __restrict__ Wt,
    const float* __restrict__ bias, void* __restrict__ C,
    int N, int K, float oscale)
{
    extern __shared__ __half smh[];
    gemm_body<RELU, HOUT>(A, Wt, bias, C, N, K, oscale, smh,
                          blockIdx.y * gg::BM, blockIdx.x * gg::BN);
}

__global__ void __launch_bounds__(256, 2) gemm_qkv_h(
    const __half* __restrict__ X,
    const __half* __restrict__ Wq, const float* __restrict__ bq, __half* __restrict__ q,
    const __half* __restrict__ Wk, const float* __restrict__ bk, __half* __restrict__ k,
    const __half* __restrict__ Wv, const float* __restrict__ bv, __half* __restrict__ v)
{
    extern __shared__ __half smh[];
    const __half* W;
    const float* bi;
    __half* C;
    float sc = 1.f;
    if (blockIdx.z == 0)      { W = Wq; bi = bq; C = q; sc = 0.125f; }
    else if (blockIdx.z == 1) { W = Wk; bi = bk; C = k; }
    else                      { W = Wv; bi = bv; C = v; }
    gemm_body<false, true>(X, W, bi, C, cfg::D_MODEL, cfg::D_MODEL, sc, smh,
                           blockIdx.y * gg::BM, blockIdx.x * gg::BN);
}

// ---------- flash attention (fp16, BKV=64, 4-stage, ldmatrix V) -------------
namespace fa {
constexpr int BQ  = 128;
constexpr int BKV = 64;
constexpr int STG = 4;
constexpr int LDK  = 36;   // u32 per K token row (32 d-pairs + 4)
constexpr int LDVH = 72;   // halves per V token row (64 + 8 pad) = 144 B
constexpr int LDP  = 36;   // u32 per P row (32 token-pairs + 4)
constexpr int K_STAGE_U32 = BKV * LDK;        // 2304
constexpr int V_STAGE_U32 = BKV * LDVH / 2;   // 2304
constexpr int SMEM_U32 = STG * (K_STAGE_U32 + V_STAGE_U32) + BQ * LDP; // 23040
constexpr int SMEM_BYTES = SMEM_U32 * 4;      // 92160
}

__global__ void __launch_bounds__(256, 2) flash_h(
    const __half* __restrict__ Q, const __half* __restrict__ K,
    const __half* __restrict__ V, __half* __restrict__ O)
{
    using namespace fa;
    extern __shared__ uint32_t sm[];
    uint32_t* Ks = sm;
    uint32_t* Vs = sm + STG * K_STAGE_U32;
    uint32_t* Ps = Vs + STG * V_STAGE_U32;
    __half*   Vsh = reinterpret_cast<__half*>(Vs);

    const int tid  = threadIdx.x;
    const int lane = tid & 31;
    const int warp = tid >> 5;
    const int grp  = lane >> 2;
    const int tg   = lane & 3;
    const int bh   = blockIdx.y;
    const int b    = bh >> 4;
    const int h    = bh & 15;
    const int bm   = blockIdx.x * BQ;
    const int wrow = warp * 16;

    const __half* Kp = K + (size_t)b * cfg::SEQ * 1024 + h * 64;
    const __half* Vp = V + (size_t)b * cfg::SEQ * 1024 + h * 64;

    // Q fragments direct from gmem (pre-scaled fp16)
    uint32_t qf[4][4];
    {
        const size_t tok0 = (size_t)b * cfg::SEQ + bm + wrow + grp;
        const uint32_t* q0 = reinterpret_cast<const uint32_t*>(
            Q + tok0 * 1024 + h * 64);
        const uint32_t* q1 = reinterpret_cast<const uint32_t*>(
            Q + (tok0 + 8) * 1024 + h * 64);
        #pragma unroll
        for (int ks = 0; ks < 4; ks++) {
            qf[ks][0] = q0[ks * 8 + tg    ];
            qf[ks][1] = q1[ks * 8 + tg    ];
            qf[ks][2] = q0[ks * 8 + tg + 4];
            qf[ks][3] = q1[ks * 8 + tg + 4];
        }
    }

    const int krow  = tid >> 3;           // 0..31
    const int kcol  = (tid & 7) * 4;      // u32
    const int vcolh = (tid & 7) * 8;      // halves

    auto issue_kv = [&](int t) {
        const int bf = t & (STG - 1);
        #pragma unroll
        for (int i = 0; i < 2; i++) {
            int r = krow + i * 32;
            cp16(&Ks[(bf * BKV + r) * LDK + kcol],
                 Kp + (size_t)(t * BKV + r) * 1024 + kcol * 2);
            cp16(&Vsh[(bf * BKV + r) * LDVH + vcolh],
                 Vp + (size_t)(t * BKV + r) * 1024 + vcolh);
        }
    };

    issue_kv(0); cp_commit();
    issue_kv(1); cp_commit();
    issue_kv(2); cp_commit();

    // ldmatrix lane mappings
    const uint32_t KsBase = (uint32_t)__cvta_generic_to_shared(Ks);
    const int kTok = (lane & 7) + ((lane & 16) ? 8 : 0);
    const int kOffU = (lane & 8) ? 4 : 0;
    const uint32_t kLane = (uint32_t)((kTok * LDK + kOffU) * 4);

    const uint32_t VsBase = (uint32_t)__cvta_generic_to_shared(Vs);
    const uint32_t vLane = (uint32_t)(((lane & 15) * LDVH
                                       + ((lane & 16) ? 8 : 0)) * 2);

    const uint32_t PsBase = (uint32_t)__cvta_generic_to_shared(Ps);
    const uint32_t pLane = (uint32_t)(((wrow + (lane & 15)) * LDP
                                       + ((lane & 16) ? 4 : 0)) * 4);

    float oacc[8][4];
    #pragma unroll
    for (int ni = 0; ni < 8; ni++)
        #pragma unroll
        for (int j = 0; j < 4; j++) oacc[ni][j] = 0.f;
    float m0 = -3.402823466e38f, m1 = -3.402823466e38f;
    float l0 = 0.f, l1 = 0.f;

    constexpr int NT = cfg::SEQ / BKV;   // 32
    for (int t = 0; t < NT; t++) {
        cp_wait<2>();
        __syncthreads();
        if (t + 3 < NT) issue_kv(t + 3);
        cp_commit();

        const int buf = t & (STG - 1);

        // ---- S = Qs @ K^T  (128 x 64, k=64 dims) ----
        float sacc[8][4];
        #pragma unroll
        for (int ni = 0; ni < 8; ni++)
            #pragma unroll
            for (int j = 0; j < 4; j++) sacc[ni][j] = 0.f;

        const uint32_t kStage = KsBase + (uint32_t)(buf * K_STAGE_U32 * 4) + kLane;
        #pragma unroll
        for (int ks = 0; ks < 4; ks++) {
            uint32_t bf[8][2];
            #pragma unroll
            for (int ng = 0; ng < 4; ng++) {
                uint32_t r[4];
                ldsm_x4(r, kStage + (uint32_t)((ng * 16 * LDK + ks * 8) * 4));
                bf[ng * 2    ][0] = r[0]; bf[ng * 2    ][1] = r[1];
                bf[ng * 2 + 1][0] = r[2]; bf[ng * 2 + 1][1] = r[3];
            }
            #pragma unroll
            for (int ni = 0; ni < 8; ni++)
                mma_f16(sacc[ni], qf[ks], bf[ni]);
        }

        // ---- online softmax (rows grp / grp+8) ----
        float mx0 = -3.402823466e38f, mx1 = -3.402823466e38f;
        #pragma unroll
        for (int ni = 0; ni < 8; ni++) {
            mx0 = fmaxf(mx0, fmaxf(sacc[ni][0], sacc[ni][1]));
            mx1 = fmaxf(mx1, fmaxf(sacc[ni][2], sacc[ni][3]));
        }
        mx0 = fmaxf(mx0, __shfl_xor_sync(0xffffffffu, mx0, 1));
        mx0 = fmaxf(mx0, __shfl_xor_sync(0xffffffffu, mx0, 2));
        mx1 = fmaxf(mx1, __shfl_xor_sync(0xffffffffu, mx1, 1));
        mx1 = fmaxf(mx1, __shfl_xor_sync(0xffffffffu, mx1, 2));

        const float mn0 = fmaxf(m0, mx0);
        const float mn1 = fmaxf(m1, mx1);
        const float a0  = __expf(m0 - mn0);
        const float a1  = __expf(m1 - mn1);
        m0 = mn0; m1 = mn1;

        float rs0 = 0.f, rs1 = 0.f;
        #pragma unroll
        for (int ni = 0; ni < 8; ni++) {
            float p0 = __expf(sacc[ni][0] - m0);
            float p1 = __expf(sacc[ni][1] - m0);
            float p2 = __expf(sacc[ni][2] - m1);
            float p3 = __expf(sacc[ni][3] - m1);
            rs0 += p0 + p1;
            rs1 += p2 + p3;
            __half2 hA = __floats2half2_rn(p0, p1);
            __half2 hB = __floats2half2_rn(p2, p3);
            Ps[(wrow + grp    ) * LDP + ni * 4 + tg] = *reinterpret_cast<uint32_t*>(&hA);
            Ps[(wrow + grp + 8) * LDP + ni * 4 + tg] = *reinterpret_cast<uint32_t*>(&hB);
        }
        l0 = l0 * a0 + rs0;
        l1 = l1 * a1 + rs1;
        #pragma unroll
        for (int ni = 0; ni < 8; ni++) {
            oacc[ni][0] *= a0; oacc[ni][1] *= a0;
            oacc[ni][2] *= a1; oacc[ni][3] *= a1;
        }
        __syncwarp();

        // ---- O += P @ V  (k = 64 tokens); P via ldmatrix, V via ldmatrix.trans
        const uint32_t vStage = VsBase + (uint32_t)(buf * V_STAGE_U32 * 4) + vLane;
        #pragma unroll
        for (int ks = 0; ks < 4; ks++) {
            uint32_t af[4];
            ldsm_x4(af, PsBase + pLane + (uint32_t)(ks * 8 * 4));
            #pragma unroll
            for (int ng = 0; ng < 4; ng++) {
                uint32_t r[4];
                ldsm_x4_t(r, vStage + (uint32_t)((ks * 16 * LDVH + ng * 16) * 2));
                mma_f16(oacc[ng * 2    ], af, &r[0]);
                mma_f16(oacc[ng * 2 + 1], af, &r[2]);
            }
        }
        __syncwarp();
    }

    l0 += __shfl_xor_sync(0xffffffffu, l0, 1);
    l0 += __shfl_xor_sync(0xffffffffu, l0, 2);
    l1 += __shfl_xor_sync(0xffffffffu, l1, 1);
    l1 += __shfl_xor_sync(0xffffffffu, l1, 2);
    const float inv0 = 1.f / l0;
    const float inv1 = 1.f / l1;

    const size_t tok0 = (size_t)b * cfg::SEQ + bm + wrow + grp;
    #pragma unroll
    for (int ni = 0; ni < 8; ni++) {
        const int c = h * 64 + ni * 8 + tg * 2;
        *reinterpret_cast<__half2*>(&O[tok0 * 1024 + c]) =
            __floats2half2_rn(oacc[ni][0] * inv0, oacc[ni][1] * inv0);
        *reinterpret_cast<__half2*>(&O[(tok0 + 8) * 1024 + c]) =
            __floats2half2_rn(oacc[ni][2] * inv1, oacc[ni][3] * inv1);
    }
}

// ------------------------------ add + LayerNorm ----------------------------
template <bool DUAL>
__global__ void __launch_bounds__(256) add_ln_kernel(
    const float* __restrict__ a, const float* __restrict__ b,
    const float* __restrict__ gamma, const float* __restrict__ beta,
    float* __restrict__ outp, __half* __restrict__ outh)
{
    const size_t row = blockIdx.x;
    const float* pa = a + row * cfg::D_MODEL;
    const float* pb = b + row * cfg::D_MODEL;
    float* po = outp + row * cfg::D_MODEL;
    __half* ph = DUAL ? outh + row * cfg::D_MODEL : nullptr;
    const int tid = threadIdx.x;

    float v[4];
    float s = 0.f, sq = 0.f;
    #pragma unroll
    for (int i = 0; i < 4; i++) {
        const int c = i * 256 + tid;
        v[i] = pa[c] + pb[c];
        s += v[i];
        sq += v[i] * v[i];
    }

    __shared__ float r1[8], r2[8];
    #pragma unroll
    for (int o = 16; o > 0; o >>= 1) {
        s  += __shfl_xor_sync(0xffffffffu, s, o);
        sq += __shfl_xor_sync(0xffffffffu, sq, o);
    }
    if ((tid & 31) == 0) { r1[tid >> 5] = s; r2[tid >> 5] = sq; }
    __syncthreads();
    s = 0.f; sq = 0.f;
    #pragma unroll
    for (int j = 0; j < 8; j++) { s += r1[j]; sq += r2[j]; }

    const float mu   = s * (1.f / cfg::D_MODEL);
    const float var  = sq * (1.f / cfg::D_MODEL) - mu * mu;
    const float rstd = rsqrtf(var + 1e-5f);

    #pragma unroll
    for (int i = 0; i < 4; i++) {
        const int c = i * 256 + tid;
        const float r = (v[i] - mu) * rstd * __ldg(&gamma[c]) + __ldg(&beta[c]);
        po[c] = r;
        if (DUAL) ph[c] = __float2half_rn(r);
    }
}

// ------------------------------ launch -------------------------------------
extern "C" void kernel_launch(void* const* d_in, const int* in_sizes, int n_in,
                              void* d_out, int out_size)
{
    using namespace cfg;
    const float* x   = (const float*)d_in[0];
    const float* Wq  = (const float*)d_in[1];
    const float* bq  = (const float*)d_in[2];
    const float* Wk  = (const float*)d_in[3];
    const float* bk_ = (const float*)d_in[4];
    const float* Wv  = (const float*)d_in[5];
    const float* bv  = (const float*)d_in[6];
    const float* Wo  = (const float*)d_in[7];
    const float* bo  = (const float*)d_in[8];
    const float* W1  = (const float*)d_in[9];
    const float* b1  = (const float*)d_in[10];
    const float* W2  = (const float*)d_in[11];
    const float* b2  = (const float*)d_in[12];
    const float* g1  = (const float*)d_in[13];
    const float* be1 = (const float*)d_in[14];
    const float* g2  = (const float*)d_in[15];
    const float* be2 = (const float*)d_in[16];
    float* out = (float*)d_out;

    __half *xh, *qh, *kh, *vh, *ah, *hh, *fh;
    __half *wtq, *wtk, *wtv, *wto, *wt1, *wt2;
    float *s1, *hf;
    cudaGetSymbolAddress((void**)&xh,  g_xh);
    cudaGetSymbolAddress((void**)&qh,  g_qh);
    cudaGetSymbolAddress((void**)&kh,  g_kh);
    cudaGetSymbolAddress((void**)&vh,  g_vh);
    cudaGetSymbolAddress((void**)&ah,  g_ah);
    cudaGetSymbolAddress((void**)&hh,  g_hh);
    cudaGetSymbolAddress((void**)&fh,  g_fh);
    cudaGetSymbolAddress((void**)&s1,  g_s1);
    cudaGetSymbolAddress((void**)&hf,  g_hf);
    cudaGetSymbolAddress((void**)&wtq, g_wtq);
    cudaGetSymbolAddress((void**)&wtk, g_wtk);
    cudaGetSymbolAddress((void**)&wtv, g_wtv);
    cudaGetSymbolAddress((void**)&wto, g_wto);
    cudaGetSymbolAddress((void**)&wt1, g_wt1);
    cudaGetSymbolAddress((void**)&wt2, g_wt2);

    static bool attr_done = false;
    if (!attr_done) {
        cudaFuncSetAttribute(flash_h,
                             cudaFuncAttributeMaxDynamicSharedMemorySize,
                             fa::SMEM_BYTES);
        cudaFuncSetAttribute(gemm_h<false, false>,
                             cudaFuncAttributeMaxDynamicSharedMemorySize,
                             gg::SMEM_BYTES);
        cudaFuncSetAttribute(gemm_h<true, true>,
                             cudaFuncAttributeMaxDynamicSharedMemorySize,
                             gg::SMEM_BYTES);
        cudaFuncSetAttribute(gemm_qkv_h,
                             cudaFuncAttributeMaxDynamicSharedMemorySize,
                             gg::SMEM_BYTES);
        attr_done = true;
    }

    // 0) conversions: x -> fp16; weights -> transposed fp16 [N][K]
    f2h_kernel<<<(NTOK * D_MODEL) / 1024, 256>>>(x, xh);
    {
        dim3 blk(32, 8);
        wT4_kernel<<<dim3(32, 32, 4), blk>>>(Wq, wtq, Wk, wtk, Wv, wtv, Wo, wto);
        wT2_kernel<<<dim3(128, 32, 2), blk>>>(W1, wt1, W2, wt2);
    }

    // 1) QKV projections (q pre-scaled by 1/8), fp16 outputs
    {
        dim3 grid(D_MODEL / gg::BN, NTOK / gg::BM, 3);
        gemm_qkv_h<<<grid, 256, gg::SMEM_BYTES>>>(
            xh, wtq, bq, qh, wtk, bk_, kh, wtv, bv, vh);
    }

    // 2-4) flash attention -> ah (fp16)
    {
        dim3 grid(SEQ / fa::BQ, BATCH * NHEADS);
        flash_h<<<grid, 256, fa::SMEM_BYTES>>>(qh, kh, vh, ah);
    }

    // 5) output projection -> s1 (fp32)
    {
        dim3 grid(D_MODEL / gg::BN, NTOK / gg::BM);
        gemm_h<false, false><<<grid, 256, gg::SMEM_BYTES>>>(
            ah, wto, bo, s1, D_MODEL, D_MODEL, 1.f);
    }

    // 6) h = LN(x + s1): fp32 + fp16 outputs
    add_ln_kernel<true><<<NTOK, 256>>>(x, s1, g1, be1, hf, hh);

    // 7) ff = relu(h @ W1 + b1) -> fh (fp16)
    {
        dim3 grid(DFF / gg::BN, NTOK / gg::BM);
        gemm_h<true, true><<<grid, 256, gg::SMEM_BYTES>>>(
            hh, wt1, b1, fh, DFF, D_MODEL, 1.f);
    }

    // 8) ff2 = fh @ W2 + b2 -> s1 (fp32)
    {
        dim3 grid(D_MODEL / gg::BN, NTOK / gg::BM);
        gemm_h<false, false><<<grid, 256, gg::SMEM_BYTES>>>(
            fh, wt2, b2, s1, D_MODEL, DFF, 1.f);
    }

    // 9) out = LN(h + ff2)
    add_ln_kernel<false><<<NTOK, 256>>>(hf, s1, g2, be2, out, nullptr);
}